// round 1
// baseline (speedup 1.0000x reference)
#include <cuda_runtime.h>
#include <cuda_fp16.h>

// Problem constants (fixed by the dataset)
#define BT_  1024   // B*T = 4*256
#define IN_  512
#define OUT_ 512

// Scratch (no cudaMalloc allowed): decoded fp32 operands + fp16 GEMM result
__device__ float  g_x[BT_ * IN_];    // 2 MB
__device__ float  g_w[OUT_ * IN_];   // 1 MB
__device__ __half g_c[BT_ * OUT_];   // 1 MB

// ---------------------------------------------------------------------------
// Packed f32x2 helpers (Blackwell): two independent fp32 FMAs per op, each
// rounded exactly like scalar FFMA -> preserves bit-exact sequential sums.
// ---------------------------------------------------------------------------
__device__ __forceinline__ unsigned long long pack2(float lo, float hi) {
    unsigned long long r;
    asm("mov.b64 %0, {%1, %2};" : "=l"(r) : "f"(lo), "f"(hi));
    return r;
}
__device__ __forceinline__ void unpack2(unsigned long long v, float& lo, float& hi) {
    asm("mov.b64 {%0, %1}, %2;" : "=f"(lo), "=f"(hi) : "l"(v));
}
__device__ __forceinline__ unsigned long long fma2(unsigned long long a,
                                                   unsigned long long b,
                                                   unsigned long long c) {
    unsigned long long d;
    asm("fma.rn.f32x2 %0, %1, %2, %3;" : "=l"(d) : "l"(a), "l"(b), "l"(c));
    return d;
}

// ---------------------------------------------------------------------------
// Kernel 1: decode pulse bits -> exact fp16 value in fp32.
// One thread per element: 64B contiguous read, 4B write. HBM-bound.
// ---------------------------------------------------------------------------
__global__ void decode_kernel(const float* __restrict__ xp,
                              const float* __restrict__ wp) {
    int idx = blockIdx.x * blockDim.x + threadIdx.x;
    const int NX = BT_ * IN_;
    const int NW = OUT_ * IN_;
    if (idx >= NX + NW) return;

    const float* src;
    float* dst;
    int e;
    if (idx < NX) { src = xp; dst = g_x; e = idx; }
    else          { src = wp; dst = g_w; e = idx - NX; }

    const float4* p = reinterpret_cast<const float4*>(src + (size_t)e * 16);
    unsigned u = 0u;
#pragma unroll
    for (int q = 0; q < 4; ++q) {
        float4 v = p[q];
        u |= (__float_as_uint(v.x) ? 1u : 0u) << (4 * q + 0);
        u |= (__float_as_uint(v.y) ? 1u : 0u) << (4 * q + 1);
        u |= (__float_as_uint(v.z) ? 1u : 0u) << (4 * q + 2);
        u |= (__float_as_uint(v.w) ? 1u : 0u) << (4 * q + 3);
    }
    dst[e] = __half2float(__ushort_as_half((unsigned short)u));
}

// ---------------------------------------------------------------------------
// Kernel 2: register-blocked GEMM C[1024,512] = X[1024,512] * W^T[512,512]
// with strictly sequential k-accumulation per output element (bit-exact).
// BM=64, BN=64, BK=32; 128 threads; micro-tile TM=4 x TN=8 via f32x2 FMA.
// ---------------------------------------------------------------------------
#define BM  64
#define BN  64
#define BK  32
#define TM  4
#define TN  8

__global__ __launch_bounds__(128) void gemm_kernel() {
    __shared__ float Xs[BK][BM + 4];   // +4 pad: conflict relief, keeps 16B align
    __shared__ float Ws[BK][BN + 4];

    const int tid  = threadIdx.x;
    const int row0 = blockIdx.y * BM;
    const int col0 = blockIdx.x * BN;

    // compute mapping: 8 col-groups x 16 row-groups
    const int tcol = tid & 7;    // cols  = col0 + tcol*TN .. +TN-1
    const int trow = tid >> 3;   // rows  = row0 + trow*TM .. +TM-1

    unsigned long long acc[TM][TN / 2];
#pragma unroll
    for (int i = 0; i < TM; ++i)
#pragma unroll
        for (int j = 0; j < TN / 2; ++j) acc[i][j] = 0ull;

    const float* Xg = g_x + (size_t)row0 * IN_;
    const float* Wg = g_w + (size_t)col0 * IN_;

    for (int kt = 0; kt < IN_; kt += BK) {
        // --- fill tiles (transposed into smem: [k][m] / [k][n]) ---
#pragma unroll
        for (int f = 0; f < 4; ++f) {
            int id = tid + 128 * f;          // 0..511
            int r  = id >> 3;                // 0..63
            int cq = id & 7;                 // 0..7 -> k-quad
            float4 vx = *reinterpret_cast<const float4*>(Xg + (size_t)r * IN_ + kt + cq * 4);
            Xs[cq * 4 + 0][r] = vx.x;
            Xs[cq * 4 + 1][r] = vx.y;
            Xs[cq * 4 + 2][r] = vx.z;
            Xs[cq * 4 + 3][r] = vx.w;
            float4 vw = *reinterpret_cast<const float4*>(Wg + (size_t)r * IN_ + kt + cq * 4);
            Ws[cq * 4 + 0][r] = vw.x;
            Ws[cq * 4 + 1][r] = vw.y;
            Ws[cq * 4 + 2][r] = vw.z;
            Ws[cq * 4 + 3][r] = vw.w;
        }
        __syncthreads();

        // --- compute: strictly ascending k per output element ---
#pragma unroll 8
        for (int k = 0; k < BK; ++k) {
            float4 xv = *reinterpret_cast<const float4*>(&Xs[k][trow * TM]);
            float4 wa = *reinterpret_cast<const float4*>(&Ws[k][tcol * TN]);
            float4 wb = *reinterpret_cast<const float4*>(&Ws[k][tcol * TN + 4]);
            unsigned long long w2[4];
            w2[0] = pack2(wa.x, wa.y);
            w2[1] = pack2(wa.z, wa.w);
            w2[2] = pack2(wb.x, wb.y);
            w2[3] = pack2(wb.z, wb.w);
            float xr[4] = {xv.x, xv.y, xv.z, xv.w};
#pragma unroll
            for (int i = 0; i < TM; ++i) {
                unsigned long long xd = pack2(xr[i], xr[i]);
#pragma unroll
                for (int j = 0; j < TN / 2; ++j)
                    acc[i][j] = fma2(xd, w2[j], acc[i][j]);
            }
        }
        __syncthreads();
    }

    // --- epilogue: fp32 -> fp16 (RNE), store compact half result ---
    const int orow = row0 + trow * TM;
    const int ocol = col0 + tcol * TN;
#pragma unroll
    for (int i = 0; i < TM; ++i) {
        __half2* crow = reinterpret_cast<__half2*>(g_c + (size_t)(orow + i) * OUT_ + ocol);
#pragma unroll
        for (int j = 0; j < TN / 2; ++j) {
            float lo, hi;
            unpack2(acc[i][j], lo, hi);
            crow[j] = __floats2half2_rn(lo, hi);
        }
    }
}

// ---------------------------------------------------------------------------
// Kernel 3: encode fp16 result -> pulse bits. One thread per output float.
// Perfectly coalesced 4B stores; half reads are L1-broadcast (16x reuse).
// ---------------------------------------------------------------------------
__global__ void encode_kernel(float* __restrict__ out) {
    int idx = blockIdx.x * blockDim.x + threadIdx.x;
    const int N = BT_ * OUT_ * 16;
    if (idx >= N) return;
    int e = idx >> 4;
    int k = idx & 15;
    unsigned short u = __half_as_ushort(g_c[e]);
    out[idx] = (float)((u >> k) & 1u);
}

// ---------------------------------------------------------------------------
extern "C" void kernel_launch(void* const* d_in, const int* in_sizes, int n_in,
                              void* d_out, int out_size) {
    const float* xp = (const float*)d_in[0];   // x_pulse [4,256,512,16]
    const float* wp = (const float*)d_in[1];   // w_pulse [512,512,16]
    float* out = (float*)d_out;                // [4,256,512,16]

    (void)in_sizes; (void)n_in; (void)out_size;

    // 1) decode both operand pulse arrays
    const int n_dec = BT_ * IN_ + OUT_ * IN_;  // 786432
    decode_kernel<<<(n_dec + 255) / 256, 256>>>(xp, wp);

    // 2) bit-exact sequential-k GEMM + RNE fp16 epilogue
    dim3 grid(OUT_ / BN, BT_ / BM);            // (8, 16) = 128 CTAs
    gemm_kernel<<<grid, 128>>>();

    // 3) encode output pulses
    const int n_enc = BT_ * OUT_ * 16;         // 8388608
    encode_kernel<<<(n_enc + 255) / 256, 256>>>(out);
}

// round 2
// speedup vs baseline: 1.1016x; 1.1016x over previous
#include <cuda_runtime.h>
#include <cuda_fp16.h>

// Problem constants (fixed by the dataset)
#define BT_  1024   // B*T = 4*256
#define IN_  512
#define OUT_ 512

// Scratch: decoded fp32 operands (no device allocation allowed)
__device__ float g_x[BT_ * IN_];    // 2 MB
__device__ float g_w[OUT_ * IN_];   // 1 MB

// ---------------------------------------------------------------------------
// Packed f32x2 FMA (Blackwell): two independent fp32 FMAs, each rounded
// exactly like scalar FFMA -> preserves bit-exact sequential accumulation.
// ---------------------------------------------------------------------------
__device__ __forceinline__ unsigned long long fma2(unsigned long long a,
                                                   unsigned long long b,
                                                   unsigned long long c) {
    unsigned long long d;
    asm("fma.rn.f32x2 %0, %1, %2, %3;" : "=l"(d) : "l"(a), "l"(b), "l"(c));
    return d;
}

// ---------------------------------------------------------------------------
// Kernel 1: decode pulse bits -> exact fp16 value in fp32.
// 2 elements per thread: 8x LDG.128 (MLP=8), float2 store. HBM-bound.
// Pulse floats are exactly 0.0f or 1.0f, so bit 23 of the raw word is the bit.
// ---------------------------------------------------------------------------
__global__ void decode_kernel(const uint4* __restrict__ xp,
                              const uint4* __restrict__ wp) {
    int t = blockIdx.x * blockDim.x + threadIdx.x;
    const int NX = BT_ * IN_;
    const int NTOT = NX + OUT_ * IN_;
    int e0 = t * 2;
    if (e0 >= NTOT) return;

    const uint4* src;
    float* dst;
    int e;
    if (e0 < NX) { src = xp; dst = g_x; e = e0; }
    else         { src = wp; dst = g_w; e = e0 - NX; }

    uint4 v[8];
#pragma unroll
    for (int q = 0; q < 8; ++q) v[q] = src[(size_t)e * 4 + q];

    float r[2];
#pragma unroll
    for (int h = 0; h < 2; ++h) {
        unsigned u = 0u;
#pragma unroll
        for (int q = 0; q < 4; ++q) {
            uint4 w4 = v[h * 4 + q];
            u |= ((w4.x >> 23) & 1u) << (4 * q + 0);
            u |= ((w4.y >> 23) & 1u) << (4 * q + 1);
            u |= ((w4.z >> 23) & 1u) << (4 * q + 2);
            u |= ((w4.w >> 23) & 1u) << (4 * q + 3);
        }
        r[h] = __half2float(__ushort_as_half((unsigned short)u));
    }
    *reinterpret_cast<float2*>(dst + e) = make_float2(r[0], r[1]);
}

// ---------------------------------------------------------------------------
// Kernel 2 (fused): GEMM with strictly-sequential-k fp32 accumulation,
// RNE fp32->fp16, and pulse-bit encode written straight to the output.
//
// Tile 64x64, 128 threads, TM=4 x TN=8 per thread; acc packs column pairs
// in f32x2. X is stored DUPLICATED in smem ((x,x) pairs) and W naturally
// paired, so every fma2 operand is a direct 64-bit slice of an LDS.128 —
// no pack movs in the inner loop. Double-buffered smem (BK=16) with
// register prefetch hides GMEM latency.
// ---------------------------------------------------------------------------
#define BM  64
#define BN  64
#define BK  16
#define NT  (IN_ / BK)   // 32 tiles
#define XP  132          // dup-X pitch: 2*64 + 4 (16B-aligned rows)
#define WP  68           // W pitch: 64 + 4    (16B-aligned rows)

__device__ __forceinline__ float4 bits4(unsigned u, int s) {
    float4 f;
    f.x = __uint_as_float(((u >> (s + 0)) & 1u) * 0x3F800000u);
    f.y = __uint_as_float(((u >> (s + 1)) & 1u) * 0x3F800000u);
    f.z = __uint_as_float(((u >> (s + 2)) & 1u) * 0x3F800000u);
    f.w = __uint_as_float(((u >> (s + 3)) & 1u) * 0x3F800000u);
    return f;
}

__global__ __launch_bounds__(128) void gemm_enc_kernel(float* __restrict__ out) {
    __shared__ float Xd[2][BK][XP];   // duplicated X: [k][2m]=[k][2m+1]=x[m]
    __shared__ float Ws[2][BK][WP];   // W: [k][n]

    const int tid  = threadIdx.x;
    const int row0 = blockIdx.y * BM;
    const int col0 = blockIdx.x * BN;
    const int tcol = tid & 7;    // 8 col groups of TN=8
    const int trow = tid >> 3;   // 16 row groups of TM=4

    unsigned long long acc[4][4] = {};  // [i][j] = (C[r+i][c+2j], C[r+i][c+2j+1])

    const float* Xg = g_x + (size_t)row0 * IN_;
    const float* Wg = g_w + (size_t)col0 * IN_;

    float4 px[2], pw[2];

    // --- prologue: load + store tile 0 ---
#pragma unroll
    for (int i = 0; i < 2; ++i) {
        int f = tid + i * 128;          // 0..255
        int m = f >> 2, kq = f & 3;     // 64 rows x 4 k-quads
        px[i] = *reinterpret_cast<const float4*>(Xg + (size_t)m * IN_ + kq * 4);
        pw[i] = *reinterpret_cast<const float4*>(Wg + (size_t)m * IN_ + kq * 4);
    }
#pragma unroll
    for (int i = 0; i < 2; ++i) {
        int f = tid + i * 128;
        int m = f >> 2, kq = f & 3;
        float xv[4] = {px[i].x, px[i].y, px[i].z, px[i].w};
        float wv[4] = {pw[i].x, pw[i].y, pw[i].z, pw[i].w};
#pragma unroll
        for (int c = 0; c < 4; ++c) {
            *reinterpret_cast<float2*>(&Xd[0][kq * 4 + c][2 * m]) = make_float2(xv[c], xv[c]);
            Ws[0][kq * 4 + c][m] = wv[c];
        }
    }
    __syncthreads();

    int buf = 0;
    for (int t = 0; t < NT; ++t) {
        // prefetch next tile into registers (latency hidden under compute)
        if (t + 1 < NT) {
            int kt = (t + 1) * BK;
#pragma unroll
            for (int i = 0; i < 2; ++i) {
                int f = tid + i * 128;
                int m = f >> 2, kq = f & 3;
                px[i] = *reinterpret_cast<const float4*>(Xg + (size_t)m * IN_ + kt + kq * 4);
                pw[i] = *reinterpret_cast<const float4*>(Wg + (size_t)m * IN_ + kt + kq * 4);
            }
        }

        // compute: strictly ascending k for every output element
#pragma unroll
        for (int k = 0; k < BK; ++k) {
            ulonglong2 xa = *reinterpret_cast<const ulonglong2*>(&Xd[buf][k][8 * trow]);
            ulonglong2 xb = *reinterpret_cast<const ulonglong2*>(&Xd[buf][k][8 * trow + 4]);
            ulonglong2 wa = *reinterpret_cast<const ulonglong2*>(&Ws[buf][k][8 * tcol]);
            ulonglong2 wb = *reinterpret_cast<const ulonglong2*>(&Ws[buf][k][8 * tcol + 4]);
            unsigned long long xr[4] = {xa.x, xa.y, xb.x, xb.y};
            unsigned long long wr[4] = {wa.x, wa.y, wb.x, wb.y};
#pragma unroll
            for (int i = 0; i < 4; ++i)
#pragma unroll
                for (int j = 0; j < 4; ++j)
                    acc[i][j] = fma2(xr[i], wr[j], acc[i][j]);
        }

        // stage prefetched registers into the other buffer
        if (t + 1 < NT) {
#pragma unroll
            for (int i = 0; i < 2; ++i) {
                int f = tid + i * 128;
                int m = f >> 2, kq = f & 3;
                float xv[4] = {px[i].x, px[i].y, px[i].z, px[i].w};
                float wv[4] = {pw[i].x, pw[i].y, pw[i].z, pw[i].w};
#pragma unroll
                for (int c = 0; c < 4; ++c) {
                    *reinterpret_cast<float2*>(&Xd[buf ^ 1][kq * 4 + c][2 * m]) =
                        make_float2(xv[c], xv[c]);
                    Ws[buf ^ 1][kq * 4 + c][m] = wv[c];
                }
            }
        }
        __syncthreads();
        buf ^= 1;
    }

    // --- fused epilogue: fp32 -> fp16 (RNE) -> 16 pulse bits per output ---
    // Each thread writes 8 consecutive columns per row: 512B contiguous runs.
    const int cb = col0 + tcol * 8;
#pragma unroll
    for (int i = 0; i < 4; ++i) {
        int r = row0 + trow * 4 + i;
        float4* dst = reinterpret_cast<float4*>(out + ((size_t)r * OUT_ + cb) * 16);
#pragma unroll
        for (int j = 0; j < 4; ++j) {
            float lo, hi;
            asm("mov.b64 {%0, %1}, %2;" : "=f"(lo), "=f"(hi) : "l"(acc[i][j]));
            unsigned u0 = __half_as_ushort(__float2half_rn(lo));
            unsigned u1 = __half_as_ushort(__float2half_rn(hi));
#pragma unroll
            for (int q = 0; q < 4; ++q) {
                dst[(2 * j) * 4 + q]     = bits4(u0, 4 * q);
                dst[(2 * j + 1) * 4 + q] = bits4(u1, 4 * q);
            }
        }
    }
}

// ---------------------------------------------------------------------------
extern "C" void kernel_launch(void* const* d_in, const int* in_sizes, int n_in,
                              void* d_out, int out_size) {
    const uint4* xp = (const uint4*)d_in[0];   // x_pulse [4,256,512,16]
    const uint4* wp = (const uint4*)d_in[1];   // w_pulse [512,512,16]
    float* out = (float*)d_out;                // [4,256,512,16]
    (void)in_sizes; (void)n_in; (void)out_size;

    // 1) decode both operand pulse arrays (2 elements / thread)
    const int n_thr = (BT_ * IN_ + OUT_ * IN_) / 2;   // 393216
    decode_kernel<<<(n_thr + 255) / 256, 256>>>(xp, wp);

    // 2) fused bit-exact GEMM + RNE fp16 + pulse-bit encode
    dim3 grid(OUT_ / BN, BT_ / BM);                   // (8, 16) = 128 CTAs
    gemm_enc_kernel<<<grid, 128>>>(out);
}

// round 3
// speedup vs baseline: 1.1317x; 1.0274x over previous
#include <cuda_runtime.h>
#include <cuda_fp16.h>

// Problem constants (fixed by the dataset)
#define BT_  1024   // B*T = 4*256
#define IN_  512
#define OUT_ 512

// Scratch: decoded fp32 operands (no device allocation allowed)
__device__ float g_x[BT_ * IN_];    // 2 MB
__device__ float g_w[OUT_ * IN_];   // 1 MB

// ---------------------------------------------------------------------------
// Packed f32x2 FMA (Blackwell): two independent fp32 FMAs, each rounded
// exactly like scalar FFMA -> preserves bit-exact sequential accumulation.
// ---------------------------------------------------------------------------
__device__ __forceinline__ unsigned long long fma2(unsigned long long a,
                                                   unsigned long long b,
                                                   unsigned long long c) {
    unsigned long long d;
    asm("fma.rn.f32x2 %0, %1, %2, %3;" : "=l"(d) : "l"(a), "l"(b), "l"(c));
    return d;
}

// ---------------------------------------------------------------------------
// Kernel 1: decode pulse bits -> exact fp16 value in fp32.
// 4 elements per thread: 16x LDG.128 in flight (MLP=16), float4 store.
// Pulse floats are exactly 0.0f or 1.0f, so bit 23 of the raw word is the bit.
// ---------------------------------------------------------------------------
__global__ void decode_kernel(const uint4* __restrict__ xp,
                              const uint4* __restrict__ wp) {
    int t = blockIdx.x * blockDim.x + threadIdx.x;
    const int NX = BT_ * IN_;              // 524288 (divisible by 4)
    const int NTOT = NX + OUT_ * IN_;      // 786432
    int e0 = t * 4;
    if (e0 >= NTOT) return;

    const uint4* src;
    float* dst;
    int e;
    if (e0 < NX) { src = xp; dst = g_x; e = e0; }
    else         { src = wp; dst = g_w; e = e0 - NX; }

    uint4 v[16];
#pragma unroll
    for (int q = 0; q < 16; ++q) v[q] = src[(size_t)e * 4 + q];

    float4 r;
    float* rp = &r.x;
#pragma unroll
    for (int h = 0; h < 4; ++h) {
        unsigned u = 0u;
#pragma unroll
        for (int q = 0; q < 4; ++q) {
            uint4 w4 = v[h * 4 + q];
            u |= ((w4.x >> 23) & 1u) << (4 * q + 0);
            u |= ((w4.y >> 23) & 1u) << (4 * q + 1);
            u |= ((w4.z >> 23) & 1u) << (4 * q + 2);
            u |= ((w4.w >> 23) & 1u) << (4 * q + 3);
        }
        rp[h] = __half2float(__ushort_as_half((unsigned short)u));
    }
    *reinterpret_cast<float4*>(dst + e) = r;
}

// ---------------------------------------------------------------------------
// Kernel 2 (fused): bit-exact sequential-k GEMM + RNE fp16 + pulse encode.
//
// Tile 64x64, 512 threads (16 warps -> 4 warps/SMSP), TM=2 x TN=4 per thread.
// X stored duplicated in smem ((x,x) pairs); W naturally paired -> every fma2
// operand is a direct 64-bit slice of an LDS.128. Lane mapping keeps each
// warp's X load to 64B (1 wavefront, broadcast) and W load to 128B contiguous
// (1 wavefront): smem issue (32 cyc/k/SM) == fma2 issue (32 cyc/k/SM).
// Double-buffered smem (BK=16) with register prefetch.
// ---------------------------------------------------------------------------
#define BM  64
#define BN  64
#define BK  16
#define NT  (IN_ / BK)   // 32 tiles
#define XP  132          // dup-X pitch: 2*64 + 4 (rows stay 16B aligned)
#define WP  68           // W pitch: 64 + 4      (rows stay 16B aligned)

__device__ __forceinline__ float4 bits4(unsigned u, int s) {
    float4 f;
    f.x = __uint_as_float(((u >> (s + 0)) & 1u) * 0x3F800000u);
    f.y = __uint_as_float(((u >> (s + 1)) & 1u) * 0x3F800000u);
    f.z = __uint_as_float(((u >> (s + 2)) & 1u) * 0x3F800000u);
    f.w = __uint_as_float(((u >> (s + 3)) & 1u) * 0x3F800000u);
    return f;
}

__global__ __launch_bounds__(512) void gemm_enc_kernel(float* __restrict__ out) {
    __shared__ float Xd[2][BK][XP];   // duplicated X: [k][2m]=[k][2m+1]=x[m]
    __shared__ float Ws[2][BK][WP];   // W: [k][n]

    const int tid  = threadIdx.x;
    const int row0 = blockIdx.y * BM;
    const int col0 = blockIdx.x * BN;

    // warp-local mapping: contiguous smem reads per warp
    const int w  = tid >> 5;
    const int l  = tid & 31;
    const int cg = (w & 1) * 8 + (l & 7);    // 0..15 col group (4 cols)
    const int rg = (w >> 1) * 4 + (l >> 3);  // 0..31 row group (2 rows)

    unsigned long long acc[2][2] = {};  // [i][j] = (C[2rg+i][4cg+2j], ...+2j+1)

    const float* Xg = g_x + (size_t)row0 * IN_;
    const float* Wg = g_w + (size_t)col0 * IN_;

    // fill roles: threads 0..255 load X, 256..511 load W (1 float4 each/tile)
    const bool isX = tid < 256;
    const int  f   = isX ? tid : tid - 256;
    const int  fm  = f >> 2;            // 0..63 row of the tile
    const int  fkq = f & 3;             // 0..3  k-quad
    const float* src = (isX ? Xg : Wg) + (size_t)fm * IN_ + fkq * 4;

    float4 p;

    // --- prologue: tile 0 ---
    p = *reinterpret_cast<const float4*>(src);
    {
        float pv[4] = {p.x, p.y, p.z, p.w};
        if (isX) {
#pragma unroll
            for (int c = 0; c < 4; ++c)
                *reinterpret_cast<float2*>(&Xd[0][fkq * 4 + c][2 * fm]) =
                    make_float2(pv[c], pv[c]);
        } else {
#pragma unroll
            for (int c = 0; c < 4; ++c) Ws[0][fkq * 4 + c][fm] = pv[c];
        }
    }
    __syncthreads();

    int buf = 0;
    for (int t = 0; t < NT; ++t) {
        // prefetch next tile into registers
        if (t + 1 < NT)
            p = *reinterpret_cast<const float4*>(src + (t + 1) * BK);

        // compute: strictly ascending k for every output element
#pragma unroll
        for (int k = 0; k < BK; ++k) {
            ulonglong2 xr = *reinterpret_cast<const ulonglong2*>(&Xd[buf][k][4 * rg]);
            ulonglong2 wr = *reinterpret_cast<const ulonglong2*>(&Ws[buf][k][4 * cg]);
            acc[0][0] = fma2(xr.x, wr.x, acc[0][0]);
            acc[0][1] = fma2(xr.x, wr.y, acc[0][1]);
            acc[1][0] = fma2(xr.y, wr.x, acc[1][0]);
            acc[1][1] = fma2(xr.y, wr.y, acc[1][1]);
        }

        // stage prefetched registers into the other buffer
        if (t + 1 < NT) {
            float pv[4] = {p.x, p.y, p.z, p.w};
            if (isX) {
#pragma unroll
                for (int c = 0; c < 4; ++c)
                    *reinterpret_cast<float2*>(&Xd[buf ^ 1][fkq * 4 + c][2 * fm]) =
                        make_float2(pv[c], pv[c]);
            } else {
#pragma unroll
                for (int c = 0; c < 4; ++c) Ws[buf ^ 1][fkq * 4 + c][fm] = pv[c];
            }
        }
        __syncthreads();
        buf ^= 1;
    }

    // --- fused epilogue: fp32 -> fp16 (RNE) -> 16 pulse bits per output ---
    // Each thread writes 2 rows x 4 consecutive cols = 256B contiguous runs.
    const int cb = col0 + cg * 4;
#pragma unroll
    for (int i = 0; i < 2; ++i) {
        int r = row0 + rg * 2 + i;
        float4* dst = reinterpret_cast<float4*>(out + ((size_t)r * OUT_ + cb) * 16);
#pragma unroll
        for (int j = 0; j < 2; ++j) {
            float lo, hi;
            asm("mov.b64 {%0, %1}, %2;" : "=f"(lo), "=f"(hi) : "l"(acc[i][j]));
            unsigned u0 = __half_as_ushort(__float2half_rn(lo));
            unsigned u1 = __half_as_ushort(__float2half_rn(hi));
#pragma unroll
            for (int q = 0; q < 4; ++q) {
                dst[(2 * j) * 4 + q]     = bits4(u0, 4 * q);
                dst[(2 * j + 1) * 4 + q] = bits4(u1, 4 * q);
            }
        }
    }
}

// ---------------------------------------------------------------------------
extern "C" void kernel_launch(void* const* d_in, const int* in_sizes, int n_in,
                              void* d_out, int out_size) {
    const uint4* xp = (const uint4*)d_in[0];   // x_pulse [4,256,512,16]
    const uint4* wp = (const uint4*)d_in[1];   // w_pulse [512,512,16]
    float* out = (float*)d_out;                // [4,256,512,16]
    (void)in_sizes; (void)n_in; (void)out_size;

    // 1) decode both operand pulse arrays (4 elements / thread)
    const int n_thr = (BT_ * IN_ + OUT_ * IN_) / 4;   // 196608
    decode_kernel<<<(n_thr + 255) / 256, 256>>>(xp, wp);

    // 2) fused bit-exact GEMM + RNE fp16 + pulse-bit encode
    dim3 grid(OUT_ / BN, BT_ / BM);                   // (8, 16) = 128 CTAs
    gemm_enc_kernel<<<grid, 512>>>(out);
}

// round 4
// speedup vs baseline: 1.6016x; 1.4152x over previous
#include <cuda_runtime.h>
#include <cuda_fp16.h>

// Problem constants (fixed by the dataset)
#define BT_  1024   // B*T = 4*256
#define IN_  512
#define OUT_ 512

// Scratch: decoded fp32 operands (no device allocation allowed)
__device__ float g_x[BT_ * IN_];    // 2 MB
__device__ float g_w[OUT_ * IN_];   // 1 MB

// ---------------------------------------------------------------------------
// Packed f32x2 FMA (Blackwell): two independent fp32 FMAs, each rounded
// exactly like scalar FFMA -> preserves bit-exact sequential accumulation.
// ---------------------------------------------------------------------------
__device__ __forceinline__ unsigned long long fma2(unsigned long long a,
                                                   unsigned long long b,
                                                   unsigned long long c) {
    unsigned long long d;
    asm("fma.rn.f32x2 %0, %1, %2, %3;" : "=l"(d) : "l"(a), "l"(b), "l"(c));
    return d;
}
__device__ __forceinline__ unsigned long long dup2(float v) {
    unsigned long long d;
    asm("mov.b64 %0, {%1, %1};" : "=l"(d) : "f"(v));
    return d;
}

// ---------------------------------------------------------------------------
// Kernel 1: decode pulse bits -> exact fp16 value in fp32.
// 4 elements per thread: 16x LDG.128 in flight, float4 store. HBM-bound.
// Pulse floats are exactly 0.0f or 1.0f, so bit 23 of the raw word is the bit.
// ---------------------------------------------------------------------------
__global__ void decode_kernel(const uint4* __restrict__ xp,
                              const uint4* __restrict__ wp) {
    int t = blockIdx.x * blockDim.x + threadIdx.x;
    const int NX = BT_ * IN_;
    const int NTOT = NX + OUT_ * IN_;
    int e0 = t * 4;
    if (e0 >= NTOT) return;

    const uint4* src;
    float* dst;
    int e;
    if (e0 < NX) { src = xp; dst = g_x; e = e0; }
    else         { src = wp; dst = g_w; e = e0 - NX; }

    uint4 v[16];
#pragma unroll
    for (int q = 0; q < 16; ++q) v[q] = src[(size_t)e * 4 + q];

    float4 r;
    float* rp = &r.x;
#pragma unroll
    for (int h = 0; h < 4; ++h) {
        unsigned u = 0u;
#pragma unroll
        for (int q = 0; q < 4; ++q) {
            uint4 w4 = v[h * 4 + q];
            u |= ((w4.x >> 23) & 1u) << (4 * q + 0);
            u |= ((w4.y >> 23) & 1u) << (4 * q + 1);
            u |= ((w4.z >> 23) & 1u) << (4 * q + 2);
            u |= ((w4.w >> 23) & 1u) << (4 * q + 3);
        }
        rp[h] = __half2float(__ushort_as_half((unsigned short)u));
    }
    *reinterpret_cast<float4*>(dst + e) = r;
}

// ---------------------------------------------------------------------------
// Kernel 2 (fused): bit-exact sequential-k GEMM + RNE fp16 + pulse encode.
//
// Tile 64x64, 128 threads, TM=8 x TN=4 per thread, accumulators paired over
// M: acc = (C[r], C[r+1]) so the fma2 A-operand (x_r, x_{r+1}) comes straight
// out of the transposed [k][m] smem tile — no duplicated X. W is natural
// [k][n]; its (w,w) broadcast pairs are built with MOVs (alu pipe has slack).
// Smem phases/k/warp drop from 8 (R3) to 12/4warps... i.e. per SM-k from
// 128 to ~56 wavefront-cycles. Double-buffered BK=16 + register prefetch.
// ---------------------------------------------------------------------------
#define BM  64
#define BN  64
#define BK  16
#define NT  (IN_ / BK)   // 32 tiles
#define PIT 68           // smem pitch: 64 + 4 floats (rows 16B-aligned)

__device__ __forceinline__ float4 bits4(unsigned u, int s) {
    float4 f;
    f.x = __uint_as_float(((u >> (s + 0)) & 1u) * 0x3F800000u);
    f.y = __uint_as_float(((u >> (s + 1)) & 1u) * 0x3F800000u);
    f.z = __uint_as_float(((u >> (s + 2)) & 1u) * 0x3F800000u);
    f.w = __uint_as_float(((u >> (s + 3)) & 1u) * 0x3F800000u);
    return f;
}

__global__ __launch_bounds__(128, 1) void gemm_enc_kernel(float* __restrict__ out) {
    __shared__ __align__(16) float Xs[2][BK][PIT];   // transposed: [k][m]
    __shared__ __align__(16) float Ws[2][BK][PIT];   // transposed: [k][n]

    const int tid  = threadIdx.x;
    const int row0 = blockIdx.y * BM;
    const int col0 = blockIdx.x * BN;

    const int rg = tid >> 4;    // 0..7  -> rows 8*rg .. 8*rg+7
    const int cg = tid & 15;    // 0..15 -> cols 4*cg .. 4*cg+3

    // acc[p][c] = (C[8rg+2p][4cg+c], C[8rg+2p+1][4cg+c])
    unsigned long long acc[4][4] = {};

    const float* Xg = g_x + (size_t)row0 * IN_;
    const float* Wg = g_w + (size_t)col0 * IN_;

    // fill mapping: 2 float4 per array per thread per tile
    // f = tid + i*128 (0..255): m = f>>2 (0..63), kq = f&3 (k-quad)
    float4 px[2], pw[2];

    // --- prologue: tile 0 ---
#pragma unroll
    for (int i = 0; i < 2; ++i) {
        int f = tid + i * 128;
        int m = f >> 2, kq = f & 3;
        px[i] = *reinterpret_cast<const float4*>(Xg + (size_t)m * IN_ + kq * 4);
        pw[i] = *reinterpret_cast<const float4*>(Wg + (size_t)m * IN_ + kq * 4);
    }
#pragma unroll
    for (int i = 0; i < 2; ++i) {
        int f = tid + i * 128;
        int m = f >> 2, kq = f & 3;
        float xv[4] = {px[i].x, px[i].y, px[i].z, px[i].w};
        float wv[4] = {pw[i].x, pw[i].y, pw[i].z, pw[i].w};
#pragma unroll
        for (int c = 0; c < 4; ++c) {
            Xs[0][kq * 4 + c][m] = xv[c];
            Ws[0][kq * 4 + c][m] = wv[c];
        }
    }
    __syncthreads();

    int buf = 0;
    for (int t = 0; t < NT; ++t) {
        // prefetch next tile into registers
        if (t + 1 < NT) {
            int kt = (t + 1) * BK;
#pragma unroll
            for (int i = 0; i < 2; ++i) {
                int f = tid + i * 128;
                int m = f >> 2, kq = f & 3;
                px[i] = *reinterpret_cast<const float4*>(Xg + (size_t)m * IN_ + kt + kq * 4);
                pw[i] = *reinterpret_cast<const float4*>(Wg + (size_t)m * IN_ + kt + kq * 4);
            }
        }

        // compute: strictly ascending k for every output element
#pragma unroll
        for (int k = 0; k < BK; ++k) {
            ulonglong2 xa = *reinterpret_cast<const ulonglong2*>(&Xs[buf][k][8 * rg]);
            ulonglong2 xb = *reinterpret_cast<const ulonglong2*>(&Xs[buf][k][8 * rg + 4]);
            float4 wv = *reinterpret_cast<const float4*>(&Ws[buf][k][4 * cg]);
            unsigned long long wd[4];
            wd[0] = dup2(wv.x); wd[1] = dup2(wv.y);
            wd[2] = dup2(wv.z); wd[3] = dup2(wv.w);
            unsigned long long xr[4] = {xa.x, xa.y, xb.x, xb.y};
#pragma unroll
            for (int p = 0; p < 4; ++p)
#pragma unroll
                for (int c = 0; c < 4; ++c)
                    acc[p][c] = fma2(xr[p], wd[c], acc[p][c]);
        }

        // stage prefetched registers into the other buffer
        if (t + 1 < NT) {
#pragma unroll
            for (int i = 0; i < 2; ++i) {
                int f = tid + i * 128;
                int m = f >> 2, kq = f & 3;
                float xv[4] = {px[i].x, px[i].y, px[i].z, px[i].w};
                float wv[4] = {pw[i].x, pw[i].y, pw[i].z, pw[i].w};
#pragma unroll
                for (int c = 0; c < 4; ++c) {
                    Xs[buf ^ 1][kq * 4 + c][m] = xv[c];
                    Ws[buf ^ 1][kq * 4 + c][m] = wv[c];
                }
            }
        }
        __syncthreads();
        buf ^= 1;
    }

    // --- fused epilogue: fp32 -> fp16 (RNE) -> 16 pulse bits per output ---
    // Each thread writes 8 rows x 4 consecutive cols = 256B contiguous runs.
    const int cb = col0 + cg * 4;
#pragma unroll
    for (int p = 0; p < 4; ++p) {
        unsigned short u[2][4];
#pragma unroll
        for (int c = 0; c < 4; ++c) {
            float lo, hi;
            asm("mov.b64 {%0, %1}, %2;" : "=f"(lo), "=f"(hi) : "l"(acc[p][c]));
            u[0][c] = __half_as_ushort(__float2half_rn(lo));
            u[1][c] = __half_as_ushort(__float2half_rn(hi));
        }
#pragma unroll
        for (int i = 0; i < 2; ++i) {
            int r = row0 + 8 * rg + 2 * p + i;
            float4* dst = reinterpret_cast<float4*>(out + ((size_t)r * OUT_ + cb) * 16);
#pragma unroll
            for (int c = 0; c < 4; ++c)
#pragma unroll
                for (int q = 0; q < 4; ++q)
                    dst[c * 4 + q] = bits4(u[i][c], 4 * q);
        }
    }
}

// ---------------------------------------------------------------------------
extern "C" void kernel_launch(void* const* d_in, const int* in_sizes, int n_in,
                              void* d_out, int out_size) {
    const uint4* xp = (const uint4*)d_in[0];   // x_pulse [4,256,512,16]
    const uint4* wp = (const uint4*)d_in[1];   // w_pulse [512,512,16]
    float* out = (float*)d_out;                // [4,256,512,16]
    (void)in_sizes; (void)n_in; (void)out_size;

    // 1) decode both operand pulse arrays (4 elements / thread)
    const int n_thr = (BT_ * IN_ + OUT_ * IN_) / 4;   // 196608
    decode_kernel<<<(n_thr + 255) / 256, 256>>>(xp, wp);

    // 2) fused bit-exact GEMM + RNE fp16 + pulse-bit encode
    dim3 grid(OUT_ / BN, BT_ / BM);                   // (8, 16) = 128 CTAs
    gemm_enc_kernel<<<grid, 128>>>(out);
}